// round 3
// baseline (speedup 1.0000x reference)
#include <cuda_runtime.h>
#include <cuda_fp16.h>

// Problem dims (fixed by dataset): N=30000, F=16, S=8, H=16, E=300000
#define NMAX 30016

// Scratch: g in fp16: [n][9 slices][16 h]  (slice 8 = bias from bk)
__device__ __half   g_h[(size_t)NMAX * 144];
__device__ float    agg_buf[(size_t)NMAX * 16];
__device__ unsigned pooled_bits[16];
__device__ unsigned finish_count;

#define FMA2(acc, a, b) \
    asm("fma.rn.f32x2 %0, %1, %2, %3;" : "=l"(acc) : "l"(a), "l"(b), "l"(acc))
#define PACK2(dst, v) \
    asm("mov.b64 %0, {%1, %1};" : "=l"(dst) : "f"(v))
#define UNPACK2(lo, hi, v) \
    asm("mov.b64 {%0, %1}, %2;" : "=f"(lo), "=f"(hi) : "l"(v))

// ---------------------------------------------------------------------------
// Kernel P: per-node precompute.
//   Outputs per node: 10 slices x 16 h  (slices 0..7 from Wk, 8 from bk,
//   9 = x@Wr + br which initializes agg).
// Thread layout: j = tid&7 (h-pair), tq = (tid>>3)&1 (slice half: 0..4 / 5..9),
//                slot = tid>>4 (0..15), each thread owns 4 consecutive nodes.
// Block of 256 covers 64 nodes; weights broadcast from smem as 8B LDS;
// x loaded straight from global as float4 into registers.
// 20 independent f32x2 accumulator chains per thread for ILP.
// ---------------------------------------------------------------------------
__global__ void __launch_bounds__(256, 2) node_pre(const float* __restrict__ x,
                                                   const float* __restrict__ Wk,
                                                   const float* __restrict__ bk,
                                                   const float* __restrict__ Wr,
                                                   const float* __restrict__ br,
                                                   int N)
{
    __shared__ float Ms[2560];   // [t][f][h], t=0..7 Wk, t=8 bk, t=9 Wr

    int tid = threadIdx.x;
    for (int i = tid; i < 2048; i += 256) Ms[i] = Wk[i];
    Ms[2048 + tid] = bk[tid];
    Ms[2304 + tid] = Wr[tid];
    if (blockIdx.x == 0) {
        if (tid < 16) pooled_bits[tid] = 0u;
        if (tid == 0) finish_count = 0u;
    }
    __syncthreads();

    int j    = tid & 7;
    int tq   = (tid >> 3) & 1;
    int slot = tid >> 4;
    int n0   = blockIdx.x * 64 + slot * 4;
    if (n0 >= N) return;   // whole 4-node group out of range (stores all guarded anyway)

    const unsigned long long* W2 = (const unsigned long long*)Ms;
    int tbase = tq * 5;    // slices tbase..tbase+4

    unsigned long long acc[4][5];
#pragma unroll
    for (int u = 0; u < 4; u++)
#pragma unroll
        for (int t = 0; t < 5; t++) acc[u][t] = 0ull;

    const float4* X4 = (const float4*)x;

#pragma unroll
    for (int fb = 0; fb < 4; fb++) {
        float4 xv[4];
#pragma unroll
        for (int u = 0; u < 4; u++) {
            int n = n0 + u;
            int nn = (n < N) ? n : (N - 1);     // clamp (value unused if n>=N)
            xv[u] = X4[nn * 4 + fb];
        }
#pragma unroll
        for (int fi = 0; fi < 4; fi++) {
            int f = fb * 4 + fi;
            unsigned long long w[5];
#pragma unroll
            for (int t = 0; t < 5; t++)
                w[t] = W2[(tbase + t) * 128 + f * 8 + j];
#pragma unroll
            for (int u = 0; u < 4; u++) {
                float xs = (fi == 0) ? xv[u].x : (fi == 1) ? xv[u].y
                          : (fi == 2) ? xv[u].z : xv[u].w;
                unsigned long long x2;
                PACK2(x2, xs);
#pragma unroll
                for (int t = 0; t < 5; t++)
                    FMA2(acc[u][t], x2, w[t]);
            }
        }
    }

    float br0 = br[2 * j], br1 = br[2 * j + 1];

#pragma unroll
    for (int u = 0; u < 4; u++) {
        int n = n0 + u;
        if (n >= N) break;
        if (tq == 0) {
            __half2* gr = (__half2*)g_h + (size_t)n * 72 + j;
#pragma unroll
            for (int t = 0; t < 5; t++) {
                float lo, hi;
                UNPACK2(lo, hi, acc[u][t]);
                gr[t * 8] = __floats2half2_rn(lo, hi);
            }
        } else {
            __half2* gr = (__half2*)g_h + (size_t)n * 72 + j;
#pragma unroll
            for (int t = 0; t < 4; t++) {   // slices 5..8
                float lo, hi;
                UNPACK2(lo, hi, acc[u][t]);
                gr[(t + 5) * 8] = __floats2half2_rn(lo, hi);
            }
            float lo, hi;
            UNPACK2(lo, hi, acc[u][4]);     // slice 9 = x@Wr
            *(float2*)(agg_buf + (size_t)n * 16 + 2 * j) =
                make_float2(lo + br0, hi + br1);
        }
    }
}

// ---------------------------------------------------------------------------
// Kernel E: per-edge gather (fp16 g) + tiny dot + vector red scatter.
// 8 lanes per edge, lane j owns h = {2j, 2j+1}.
// ---------------------------------------------------------------------------
__global__ void __launch_bounds__(256) edge_kernel(const float* __restrict__ e,
                                                   const int* __restrict__ src,
                                                   const int* __restrict__ dst,
                                                   int E)
{
    int t = blockIdx.x * 256 + threadIdx.x;
    int gid = t >> 3;
    if (gid >= E) return;
    int j = t & 7;

    int sn = __ldg(src + gid);
    int dn = __ldg(dst + gid);

    const float4* ep = (const float4*)(e + (size_t)gid * 8);
    float4 e0 = __ldg(ep);
    float4 e1 = __ldg(ep + 1);
    float es[9] = { e0.x, e0.y, e0.z, e0.w, e1.x, e1.y, e1.z, e1.w, 1.0f };

    const __half2* gr = (const __half2*)g_h + (size_t)sn * 72 + j;
    float ax = 0.0f, ay = 0.0f;
#pragma unroll
    for (int s = 0; s < 9; s++) {
        float2 w = __half22float2(__ldg(gr + s * 8));
        ax += es[s] * w.x;
        ay += es[s] * w.y;
    }

    float* out = agg_buf + (size_t)dn * 16 + 2 * j;
    asm volatile("red.global.add.v2.f32 [%0], {%1, %2};"
                 :: "l"(out), "f"(ax), "f"(ay) : "memory");
}

// ---------------------------------------------------------------------------
// Kernel C: relu + BN + block max-reduce + atomicMax; LAST block also does
// the final dense (fused finalize).
// ---------------------------------------------------------------------------
__global__ void __launch_bounds__(256) node_post(const float* __restrict__ gamma,
                                                 const float* __restrict__ beta,
                                                 const float* __restrict__ mmean,
                                                 const float* __restrict__ mvar,
                                                 const float* __restrict__ Wd,
                                                 const float* __restrict__ bd,
                                                 float* __restrict__ out,
                                                 int N)
{
    __shared__ float wmax[8][16];
    __shared__ bool is_last;
    int n = blockIdx.x * 256 + threadIdx.x;

    float v[16];
    if (n < N) {
        const float4* ar = (const float4*)(agg_buf + (size_t)n * 16);
#pragma unroll
        for (int q = 0; q < 4; q++) {
            float4 a = ar[q];
            v[4 * q + 0] = a.x; v[4 * q + 1] = a.y;
            v[4 * q + 2] = a.z; v[4 * q + 3] = a.w;
        }
#pragma unroll
        for (int h = 0; h < 16; h++) {
            float sc = gamma[h] * rsqrtf(mvar[h] + 1e-3f);
            float sh = beta[h] - mmean[h] * sc;
            v[h] = fmaxf(v[h], 0.0f) * sc + sh;
        }
    } else {
#pragma unroll
        for (int h = 0; h < 16; h++) v[h] = -__int_as_float(0x7f800000); // -inf
    }

#pragma unroll
    for (int off = 16; off >= 1; off >>= 1) {
#pragma unroll
        for (int h = 0; h < 16; h++)
            v[h] = fmaxf(v[h], __shfl_xor_sync(0xffffffffu, v[h], off));
    }

    int wid = threadIdx.x >> 5;
    if ((threadIdx.x & 31) == 0) {
#pragma unroll
        for (int h = 0; h < 16; h++) wmax[wid][h] = v[h];
    }
    __syncthreads();

    if (threadIdx.x < 16) {
        int h = threadIdx.x;
        float m = wmax[0][h];
#pragma unroll
        for (int w = 1; w < 8; w++) m = fmaxf(m, wmax[w][h]);
        unsigned b = __float_as_uint(m);
        unsigned k = (b & 0x80000000u) ? ~b : (b | 0x80000000u);
        atomicMax(&pooled_bits[h], k);
    }

    __threadfence();
    if (threadIdx.x == 0) {
        unsigned c = atomicAdd(&finish_count, 1u);
        is_last = (c == gridDim.x - 1);
    }
    __syncthreads();
    if (!is_last) return;

    __threadfence();
    __shared__ float pooled[16];
    if (threadIdx.x < 16) {
        unsigned k = atomicAdd(&pooled_bits[threadIdx.x], 0u);
        unsigned b = (k & 0x80000000u) ? (k ^ 0x80000000u) : ~k;
        pooled[threadIdx.x] = __uint_as_float(b);
    }
    __syncthreads();
    if (threadIdx.x < 3) {
        float s = bd[threadIdx.x];
#pragma unroll
        for (int h = 0; h < 16; h++) s += pooled[h] * Wd[h * 3 + threadIdx.x];
        out[threadIdx.x] = s;
    }
}

// ---------------------------------------------------------------------------
extern "C" void kernel_launch(void* const* d_in, const int* in_sizes, int n_in,
                              void* d_out, int out_size)
{
    const float* x     = (const float*)d_in[0];
    const float* e     = (const float*)d_in[1];
    const int*   src   = (const int*)d_in[2];
    const int*   dst   = (const int*)d_in[3];
    const float* Wk    = (const float*)d_in[4];
    const float* bk    = (const float*)d_in[5];
    const float* Wr    = (const float*)d_in[6];
    const float* br    = (const float*)d_in[7];
    const float* gamma = (const float*)d_in[8];
    const float* beta  = (const float*)d_in[9];
    const float* mmean = (const float*)d_in[10];
    const float* mvar  = (const float*)d_in[11];
    const float* Wd    = (const float*)d_in[12];
    const float* bd    = (const float*)d_in[13];

    int N = in_sizes[0] / 16;   // F = 16
    int E = in_sizes[2];

    node_pre<<<(N + 63) / 64, 256>>>(x, Wk, bk, Wr, br, N);
    edge_kernel<<<(E * 8 + 255) / 256, 256>>>(e, src, dst, E);
    node_post<<<(N + 255) / 256, 256>>>(gamma, beta, mmean, mvar, Wd, bd,
                                        (float*)d_out, N);
}